// round 14
// baseline (speedup 1.0000x reference)
#include <cuda_runtime.h>
#include <cstdint>

#define NN   100000
#define NE   1600000
#define HID  64
#define H2   128
#define NSCB 98                       // ceil(NN/1024) scan blocks

typedef unsigned long long ull;

// ---------------- device scratch ----------------
__device__ __align__(16) float g_h0[(size_t)NN * HID];     // x @ W_conv
__device__ float g_dinv[NN];
__device__ int   g_deg[NN];
__device__ int   g_off[NN];
__device__ int   g_cursor[NN];
__device__ int   g_base;
__device__ int   g_srcs[NE];

// ---------------- packed fp32x2 helpers (gemm1) ----------------
__device__ __forceinline__ ull fma2(ull a, ull b, ull c) {
    ull d;
    asm("fma.rn.f32x2 %0, %1, %2, %3;" : "=l"(d) : "l"(a), "l"(b), "l"(c));
    return d;
}
__device__ __forceinline__ ull pack2(float lo, float hi) {
    ull d;
    asm("mov.b64 %0, {%1, %2};" : "=l"(d) : "f"(lo), "f"(hi));
    return d;
}
__device__ __forceinline__ float lohisum(ull a) {
    float lo, hi;
    asm("mov.b64 {%0, %1}, %2;" : "=f"(lo), "=f"(hi) : "l"(a));
    return lo + hi;
}

// ---------------- tf32 mma helpers ----------------
__device__ __forceinline__ uint32_t f2tf(float x) {
    uint32_t r;
    asm("cvt.rna.tf32.f32 %0, %1;" : "=r"(r) : "f"(x));
    return r;
}
__device__ __forceinline__ void tfsplit(float x, uint32_t& hi, uint32_t& lo) {
    hi = f2tf(x);
    lo = f2tf(x - __uint_as_float(hi));
}
__device__ __forceinline__ void mma_tf32(float* c, uint32_t a0, uint32_t a1,
                                         uint32_t a2, uint32_t a3,
                                         uint32_t b0, uint32_t b1) {
    asm("mma.sync.aligned.m16n8k8.row.col.f32.tf32.tf32.f32 "
        "{%0,%1,%2,%3}, {%4,%5,%6,%7}, {%8,%9}, {%0,%1,%2,%3};"
        : "+f"(c[0]), "+f"(c[1]), "+f"(c[2]), "+f"(c[3])
        : "r"(a0), "r"(a1), "r"(a2), "r"(a3), "r"(b0), "r"(b1));
}

// ---------------- K1: degree + edge_index tail ----------------
__global__ void k_deg_tail(const int* __restrict__ ei, float* __restrict__ tail,
                           int mode) {
    int i4 = blockIdx.x * blockDim.x + threadIdx.x;
    if (i4 == 0) g_base = 0;                           // reset for this launch
    if (i4 >= (2 * NE) / 4) return;
    int4 v = ((const int4*)ei)[i4];
    int base = i4 * 4;
    if (base >= NE) {
        atomicAdd(&g_deg[v.x], 1);
        atomicAdd(&g_deg[v.y], 1);
        atomicAdd(&g_deg[v.z], 1);
        atomicAdd(&g_deg[v.w], 1);
    }
    if (mode == 1) {
        float4 f = make_float4((float)v.x, (float)v.y, (float)v.z, (float)v.w);
        ((float4*)tail)[i4] = f;
    } else if (mode == 2) {
        longlong2 a = make_longlong2((long long)v.x, (long long)v.y);
        longlong2 b = make_longlong2((long long)v.z, (long long)v.w);
        ((longlong2*)tail)[i4 * 2]     = a;
        ((longlong2*)tail)[i4 * 2 + 1] = b;
    }
}

// ---------------- single-kernel scan: disjoint bucket bases -----------------
__global__ void k_scan() {
    __shared__ int ts[256];
    __shared__ int sbase;
    int b = blockIdx.x, t = threadIdx.x;
    int base = b * 1024 + t * 4;
    int v0 = (base + 0 < NN) ? g_deg[base + 0] : 0;
    int v1 = (base + 1 < NN) ? g_deg[base + 1] : 0;
    int v2 = (base + 2 < NN) ? g_deg[base + 2] : 0;
    int v3 = (base + 3 < NN) ? g_deg[base + 3] : 0;
    int s0 = v0, s1 = s0 + v1, s2 = s1 + v2, s3 = s2 + v3;
    ts[t] = s3;
    __syncthreads();
    for (int o = 1; o < 256; o <<= 1) {
        int x = 0;
        if (t >= o) x = ts[t - o];
        __syncthreads();
        if (t >= o) ts[t] += x;
        __syncthreads();
    }
    if (t == 0) sbase = atomicAdd(&g_base, ts[255]);
    __syncthreads();
    int excl = sbase + ((t > 0) ? ts[t - 1] : 0);
    if (base + 0 < NN) { g_off[base + 0] = excl;      g_cursor[base + 0] = excl; }
    if (base + 1 < NN) { g_off[base + 1] = excl + s0; g_cursor[base + 1] = excl + s0; }
    if (base + 2 < NN) { g_off[base + 2] = excl + s1; g_cursor[base + 2] = excl + s1; }
    if (base + 3 < NN) { g_off[base + 3] = excl + s2; g_cursor[base + 3] = excl + s2; }
}

// ---------------- K: bucket edges by dst (4 edges/thread, MLP=4) ------------
__global__ void k_bucket(const int* __restrict__ ei) {
    int i4 = blockIdx.x * blockDim.x + threadIdx.x;
    if (i4 >= NE / 4) return;
    int4 s = ((const int4*)ei)[i4];
    int4 d = ((const int4*)(ei + NE))[i4];
    int p0 = atomicAdd(&g_cursor[d.x], 1);
    int p1 = atomicAdd(&g_cursor[d.y], 1);
    int p2 = atomicAdd(&g_cursor[d.z], 1);
    int p3 = atomicAdd(&g_cursor[d.w], 1);
    g_srcs[p0] = s.x;
    g_srcs[p1] = s.y;
    g_srcs[p2] = s.z;
    g_srcs[p3] = s.w;
}

// ---------------- K2: gemm1 (h0 + dinv) ----------------
__global__ void k_gemm1(const float* __restrict__ x, const float* __restrict__ W) {
    __shared__ __align__(16) ull Wp[32 * 64];
    __shared__ __align__(16) ull xp[64 * 34];

    int t = threadIdx.x;
    for (int i = t; i < 32 * 64; i += 256) {
        int tt = i >> 6, c = i & 63;
        Wp[i] = pack2(W[(2 * tt) * 64 + c], W[(2 * tt + 1) * 64 + c]);
    }
    int row0 = blockIdx.x * 64;
    for (int i = t; i < 64 * 16; i += 256) {
        int r = i >> 4, c4 = i & 15;
        int gr = row0 + r;
        float4 v = make_float4(0.f, 0.f, 0.f, 0.f);
        if (gr < NN) v = ((const float4*)x)[(size_t)gr * 16 + c4];
        xp[r * 34 + 2 * c4]     = pack2(v.x, v.y);
        xp[r * 34 + 2 * c4 + 1] = pack2(v.z, v.w);
    }
    __syncthreads();

    int tx = t & 15, ty = t >> 4;
    ull acc[4][4];
#pragma unroll
    for (int i = 0; i < 4; i++)
#pragma unroll
        for (int j = 0; j < 4; j++) acc[i][j] = 0ull;

#pragma unroll 8
    for (int tt = 0; tt < 32; tt++) {
        ulonglong2 wA = *(const ulonglong2*)&Wp[tt * 64 + 2 * tx];
        ulonglong2 wB = *(const ulonglong2*)&Wp[tt * 64 + 32 + 2 * tx];
#pragma unroll
        for (int i = 0; i < 4; i++) {
            ull xv = xp[(4 * ty + i) * 34 + tt];
            acc[i][0] = fma2(xv, wA.x, acc[i][0]);
            acc[i][1] = fma2(xv, wA.y, acc[i][1]);
            acc[i][2] = fma2(xv, wB.x, acc[i][2]);
            acc[i][3] = fma2(xv, wB.y, acc[i][3]);
        }
    }

#pragma unroll
    for (int i = 0; i < 4; i++) {
        int gr = row0 + 4 * ty + i;
        if (gr < NN) {
            float d = rsqrtf((float)g_deg[gr] + 1.0f);
            if (tx == 0) g_dinv[gr] = d;
            float2 oA = make_float2(lohisum(acc[i][0]), lohisum(acc[i][1]));
            float2 oB = make_float2(lohisum(acc[i][2]), lohisum(acc[i][3]));
            ((float2*)g_h0)[(size_t)gr * 32 + tx]      = oA;
            ((float2*)g_h0)[(size_t)gr * 32 + 16 + tx] = oB;
        }
    }
}

// ---------------- K3: FUSED aggregate + bias+ReLU+LN + tensor GEMM2 ---------
// Warp w handles nodes node0+8w..8w+7: in-register CSR gather (MLP=4) ->
// LN -> swizzled vs store. Then the 3xTF32 GEMM2 exactly as R13.
__global__ void __launch_bounds__(256) k_epi(
        const float* __restrict__ bconv, const float* __restrict__ gamma,
        const float* __restrict__ beta, const float* __restrict__ W1,
        const float* __restrict__ b1, float* __restrict__ out) {
    __shared__ __align__(16) float vs[64 * 64];
    __shared__ __align__(16) uint2 W1fh[8 * 8 * 32];
    __shared__ __align__(16) uint2 W1fl[8 * 8 * 32];

    int t = threadIdx.x, lane = t & 31, w = t >> 5;
    int node0 = blockIdx.x * 64;

    if (node0 + 64 > NN) {
        for (int i = t; i < 64 * 64; i += 256) vs[i] = 0.f;
        __syncthreads();
    }

    float2 bc = __ldg((const float2*)bconv + lane);
    float2 gg = __ldg((const float2*)gamma + lane);
    float2 bb = __ldg((const float2*)beta + lane);

    // --- aggregate + LN phase ---
#pragma unroll
    for (int s = 0; s < 8; s++) {
        int row = 8 * w + s;
        int node = node0 + row;
        if (node < NN) {
            float dn = __ldg(&g_dinv[node]);
            float2 acc = ((const float2*)g_h0)[(size_t)node * 32 + lane];
            float n2 = dn * dn;
            acc.x *= n2;
            acc.y *= n2;

            int o0  = __ldg(&g_off[node]);
            int deg = __ldg(&g_deg[node]);
            for (int base = 0; base < deg; base += 32) {
                int sE = node;
                float wgt = 0.f;
                if (base + lane < deg) {
                    sE = g_srcs[o0 + base + lane];
                    wgt = __ldg(&g_dinv[sE]) * dn;
                }
                int cnt = min(32, deg - base);
                for (int j = 0; j < cnt; j += 4) {
                    int   s0 = __shfl_sync(0xffffffffu, sE, j);
                    int   s1 = __shfl_sync(0xffffffffu, sE, j + 1);
                    int   s2 = __shfl_sync(0xffffffffu, sE, j + 2);
                    int   s3 = __shfl_sync(0xffffffffu, sE, j + 3);
                    float n0 = __shfl_sync(0xffffffffu, wgt, j);
                    float n1 = __shfl_sync(0xffffffffu, wgt, j + 1);
                    float m2 = __shfl_sync(0xffffffffu, wgt, j + 2);
                    float n3 = __shfl_sync(0xffffffffu, wgt, j + 3);
                    float2 v0 = ((const float2*)g_h0)[(size_t)s0 * 32 + lane];
                    float2 v1 = ((const float2*)g_h0)[(size_t)s1 * 32 + lane];
                    float2 v2 = ((const float2*)g_h0)[(size_t)s2 * 32 + lane];
                    float2 v3 = ((const float2*)g_h0)[(size_t)s3 * 32 + lane];
                    acc.x += v0.x * n0; acc.y += v0.y * n0;
                    acc.x += v1.x * n1; acc.y += v1.y * n1;
                    acc.x += v2.x * m2; acc.y += v2.y * m2;
                    acc.x += v3.x * n3; acc.y += v3.y * n3;
                }
            }

            // LN
            acc.x = fmaxf(acc.x + bc.x, 0.f);
            acc.y = fmaxf(acc.y + bc.y, 0.f);
            float sm = acc.x + acc.y, sq = acc.x * acc.x + acc.y * acc.y;
#pragma unroll
            for (int o = 16; o; o >>= 1) {
                sm += __shfl_xor_sync(0xffffffffu, sm, o);
                sq += __shfl_xor_sync(0xffffffffu, sq, o);
            }
            float mu = sm * (1.f / 64.f);
            float r = rsqrtf(sq * (1.f / 64.f) - mu * mu + 1e-5f);
            float2 v = make_float2((acc.x - mu) * r * gg.x + bb.x,
                                   (acc.y - mu) * r * gg.y + bb.y);
            int sw = (2 * lane) ^ (4 * (row & 7));
            *(float2*)&vs[row * 64 + sw] = v;
        }
    }

    // --- GEMM phase (unchanged R13) ---
    int g  = lane >> 2;
    int tg = lane & 3;
    int h  = w >> 2;
    int Gr = 16 * (w & 3);

#pragma unroll
    for (int pass = 0; pass < 2; pass++) {
        int pb = pass * 64;
        __syncthreads();
        for (int i = t; i < 2048; i += 256) {
            int ks  = i >> 8;
            int nbG = (i >> 5) & 7;
            int ln  = i & 31;
            int k1  = ks * 8 + (ln & 3);
            int c   = pb + nbG * 8 + (ln >> 2);
            float bx = __ldg(&W1[k1 * 128 + c]);
            float by = __ldg(&W1[(k1 + 4) * 128 + c]);
            uint32_t hx, lx, hy, ly;
            tfsplit(bx, hx, lx);
            tfsplit(by, hy, ly);
            W1fh[i] = make_uint2(hx, hy);
            W1fl[i] = make_uint2(lx, ly);
        }
        __syncthreads();

        float acc[4][4];
#pragma unroll
        for (int nb = 0; nb < 4; nb++)
#pragma unroll
            for (int i = 0; i < 4; i++) acc[nb][i] = 0.f;

#pragma unroll
        for (int ks = 0; ks < 8; ks++) {
            int kc0 = (ks * 8 + tg)     ^ (4 * g);
            int kc1 = (ks * 8 + tg + 4) ^ (4 * g);
            float af0 = vs[(Gr + g) * 64 + kc0];
            float af1 = vs[(Gr + g + 8) * 64 + kc0];
            float af2 = vs[(Gr + g) * 64 + kc1];
            float af3 = vs[(Gr + g + 8) * 64 + kc1];
            uint32_t ah0, al0, ah1, al1, ah2, al2, ah3, al3;
            tfsplit(af0, ah0, al0);
            tfsplit(af1, ah1, al1);
            tfsplit(af2, ah2, al2);
            tfsplit(af3, ah3, al3);
#pragma unroll
            for (int nb = 0; nb < 4; nb++) {
                int fi = (ks * 8 + 4 * h + nb) * 32 + lane;
                uint2 bh = W1fh[fi];
                uint2 bl = W1fl[fi];
                mma_tf32(acc[nb], ah0, ah1, ah2, ah3, bh.x, bh.y);
                mma_tf32(acc[nb], ah0, ah1, ah2, ah3, bl.x, bl.y);
                mma_tf32(acc[nb], al0, al1, al2, al3, bh.x, bh.y);
            }
        }

#pragma unroll
        for (int nb = 0; nb < 4; nb++) {
            int col = pb + (4 * h + nb) * 8 + 2 * tg;
            float bx = __ldg(&b1[col]);
            float by = __ldg(&b1[col + 1]);
            int nA = node0 + Gr + g;
            int nB = nA + 8;
            if (nA < NN) {
                float2 o = make_float2(fmaxf(acc[nb][0] + bx, 0.f),
                                       fmaxf(acc[nb][1] + by, 0.f));
                *(float2*)&out[(size_t)nA * 128 + col] = o;
            }
            if (nB < NN) {
                float2 o = make_float2(fmaxf(acc[nb][2] + bx, 0.f),
                                       fmaxf(acc[nb][3] + by, 0.f));
                *(float2*)&out[(size_t)nB * 128 + col] = o;
            }
        }
    }
}

// ---------------- launch ----------------
extern "C" void kernel_launch(void* const* d_in, const int* in_sizes, int n_in,
                              void* d_out, int out_size) {
    const float* x      = (const float*)d_in[0];
    const int*   ei     = (const int*)d_in[1];     // int32
    const float* W_conv = (const float*)d_in[2];
    const float* b_conv = (const float*)d_in[3];
    const float* gamma  = (const float*)d_in[4];
    const float* beta   = (const float*)d_in[5];
    const float* W1     = (const float*)d_in[6];
    const float* b1     = (const float*)d_in[7];
    float* out = (float*)d_out;

    void* degp = nullptr;
    cudaGetSymbolAddress(&degp, g_deg);
    cudaMemsetAsync(degp, 0, NN * sizeof(int));

    long long n_h = (long long)NN * H2;
    long long rem = (long long)out_size - n_h;
    int mode = (rem >= (long long)4 * NE) ? 2 : (rem >= (long long)2 * NE) ? 1 : 0;

    k_deg_tail<<<((2 * NE / 4) + 255) / 256, 256>>>(ei, out + n_h, mode);
    k_scan<<<NSCB, 256>>>();
    k_bucket<<<(NE / 4 + 255) / 256, 256>>>(ei);
    k_gemm1<<<(NN + 63) / 64, 256>>>(x, W_conv);
    k_epi<<<(NN + 63) / 64, 256>>>(b_conv, gamma, beta, W1, b1, out);
}

// round 15
// speedup vs baseline: 1.0795x; 1.0795x over previous
#include <cuda_runtime.h>
#include <cstdint>

#define NN   100000
#define NE   1600000
#define HID  64
#define H2   128
#define NSCB 98                       // ceil(NN/1024) scan blocks

typedef unsigned long long ull;

// ---------------- device scratch ----------------
__device__ __align__(16) float g_h0[(size_t)NN * HID];     // x @ W_conv
__device__ __align__(16) float g_agg[(size_t)NN * HID];    // aggregated
__device__ float g_dinv[NN];
__device__ int   g_deg[NN];
__device__ int   g_off[NN];
__device__ int   g_cursor[NN];
__device__ int   g_base;
__device__ int   g_srcs[NE];

// ---------------- packed fp32x2 helpers (gemm1) ----------------
__device__ __forceinline__ ull fma2(ull a, ull b, ull c) {
    ull d;
    asm("fma.rn.f32x2 %0, %1, %2, %3;" : "=l"(d) : "l"(a), "l"(b), "l"(c));
    return d;
}
__device__ __forceinline__ ull pack2(float lo, float hi) {
    ull d;
    asm("mov.b64 %0, {%1, %2};" : "=l"(d) : "f"(lo), "f"(hi));
    return d;
}
__device__ __forceinline__ float lohisum(ull a) {
    float lo, hi;
    asm("mov.b64 {%0, %1}, %2;" : "=f"(lo), "=f"(hi) : "l"(a));
    return lo + hi;
}

// ---------------- tf32 mma helpers ----------------
__device__ __forceinline__ uint32_t f2tf(float x) {
    uint32_t r;
    asm("cvt.rna.tf32.f32 %0, %1;" : "=r"(r) : "f"(x));
    return r;
}
__device__ __forceinline__ void tfsplit(float x, uint32_t& hi, uint32_t& lo) {
    hi = f2tf(x);
    lo = f2tf(x - __uint_as_float(hi));
}
__device__ __forceinline__ void mma_tf32(float* c, uint32_t a0, uint32_t a1,
                                         uint32_t a2, uint32_t a3,
                                         uint32_t b0, uint32_t b1) {
    asm("mma.sync.aligned.m16n8k8.row.col.f32.tf32.tf32.f32 "
        "{%0,%1,%2,%3}, {%4,%5,%6,%7}, {%8,%9}, {%0,%1,%2,%3};"
        : "+f"(c[0]), "+f"(c[1]), "+f"(c[2]), "+f"(c[3])
        : "r"(a0), "r"(a1), "r"(a2), "r"(a3), "r"(b0), "r"(b1));
}

// ---------------- K1: degree + edge_index tail ----------------
__global__ void k_deg_tail(const int* __restrict__ ei, float* __restrict__ tail,
                           int mode) {
    int i4 = blockIdx.x * blockDim.x + threadIdx.x;
    if (i4 == 0) g_base = 0;                           // reset for this launch
    if (i4 >= (2 * NE) / 4) return;
    int4 v = ((const int4*)ei)[i4];
    int base = i4 * 4;
    if (base >= NE) {
        atomicAdd(&g_deg[v.x], 1);
        atomicAdd(&g_deg[v.y], 1);
        atomicAdd(&g_deg[v.z], 1);
        atomicAdd(&g_deg[v.w], 1);
    }
    if (mode == 1) {
        float4 f = make_float4((float)v.x, (float)v.y, (float)v.z, (float)v.w);
        ((float4*)tail)[i4] = f;
    } else if (mode == 2) {
        longlong2 a = make_longlong2((long long)v.x, (long long)v.y);
        longlong2 b = make_longlong2((long long)v.z, (long long)v.w);
        ((longlong2*)tail)[i4 * 2]     = a;
        ((longlong2*)tail)[i4 * 2 + 1] = b;
    }
}

// ---------------- single-kernel scan: disjoint bucket bases -----------------
__global__ void k_scan() {
    __shared__ int ts[256];
    __shared__ int sbase;
    int b = blockIdx.x, t = threadIdx.x;
    int base = b * 1024 + t * 4;
    int v0 = (base + 0 < NN) ? g_deg[base + 0] : 0;
    int v1 = (base + 1 < NN) ? g_deg[base + 1] : 0;
    int v2 = (base + 2 < NN) ? g_deg[base + 2] : 0;
    int v3 = (base + 3 < NN) ? g_deg[base + 3] : 0;
    int s0 = v0, s1 = s0 + v1, s2 = s1 + v2, s3 = s2 + v3;
    ts[t] = s3;
    __syncthreads();
    for (int o = 1; o < 256; o <<= 1) {
        int x = 0;
        if (t >= o) x = ts[t - o];
        __syncthreads();
        if (t >= o) ts[t] += x;
        __syncthreads();
    }
    if (t == 0) sbase = atomicAdd(&g_base, ts[255]);
    __syncthreads();
    int excl = sbase + ((t > 0) ? ts[t - 1] : 0);
    if (base + 0 < NN) { g_off[base + 0] = excl;      g_cursor[base + 0] = excl; }
    if (base + 1 < NN) { g_off[base + 1] = excl + s0; g_cursor[base + 1] = excl + s0; }
    if (base + 2 < NN) { g_off[base + 2] = excl + s1; g_cursor[base + 2] = excl + s1; }
    if (base + 3 < NN) { g_off[base + 3] = excl + s2; g_cursor[base + 3] = excl + s2; }
}

// ---------------- K: bucket edges by dst (4 edges/thread, MLP=4) ------------
__global__ void k_bucket(const int* __restrict__ ei) {
    int i4 = blockIdx.x * blockDim.x + threadIdx.x;
    if (i4 >= NE / 4) return;
    int4 s = ((const int4*)ei)[i4];
    int4 d = ((const int4*)(ei + NE))[i4];
    int p0 = atomicAdd(&g_cursor[d.x], 1);
    int p1 = atomicAdd(&g_cursor[d.y], 1);
    int p2 = atomicAdd(&g_cursor[d.z], 1);
    int p3 = atomicAdd(&g_cursor[d.w], 1);
    g_srcs[p0] = s.x;
    g_srcs[p1] = s.y;
    g_srcs[p2] = s.z;
    g_srcs[p3] = s.w;
}

// ---------------- K2: gemm1 (h0 + dinv) ----------------
__global__ void k_gemm1(const float* __restrict__ x, const float* __restrict__ W) {
    __shared__ __align__(16) ull Wp[32 * 64];
    __shared__ __align__(16) ull xp[64 * 34];

    int t = threadIdx.x;
    for (int i = t; i < 32 * 64; i += 256) {
        int tt = i >> 6, c = i & 63;
        Wp[i] = pack2(W[(2 * tt) * 64 + c], W[(2 * tt + 1) * 64 + c]);
    }
    int row0 = blockIdx.x * 64;
    for (int i = t; i < 64 * 16; i += 256) {
        int r = i >> 4, c4 = i & 15;
        int gr = row0 + r;
        float4 v = make_float4(0.f, 0.f, 0.f, 0.f);
        if (gr < NN) v = ((const float4*)x)[(size_t)gr * 16 + c4];
        xp[r * 34 + 2 * c4]     = pack2(v.x, v.y);
        xp[r * 34 + 2 * c4 + 1] = pack2(v.z, v.w);
    }
    __syncthreads();

    int tx = t & 15, ty = t >> 4;
    ull acc[4][4];
#pragma unroll
    for (int i = 0; i < 4; i++)
#pragma unroll
        for (int j = 0; j < 4; j++) acc[i][j] = 0ull;

#pragma unroll 8
    for (int tt = 0; tt < 32; tt++) {
        ulonglong2 wA = *(const ulonglong2*)&Wp[tt * 64 + 2 * tx];
        ulonglong2 wB = *(const ulonglong2*)&Wp[tt * 64 + 32 + 2 * tx];
#pragma unroll
        for (int i = 0; i < 4; i++) {
            ull xv = xp[(4 * ty + i) * 34 + tt];
            acc[i][0] = fma2(xv, wA.x, acc[i][0]);
            acc[i][1] = fma2(xv, wA.y, acc[i][1]);
            acc[i][2] = fma2(xv, wB.x, acc[i][2]);
            acc[i][3] = fma2(xv, wB.y, acc[i][3]);
        }
    }

#pragma unroll
    for (int i = 0; i < 4; i++) {
        int gr = row0 + 4 * ty + i;
        if (gr < NN) {
            float d = rsqrtf((float)g_deg[gr] + 1.0f);
            if (tx == 0) g_dinv[gr] = d;
            float2 oA = make_float2(lohisum(acc[i][0]), lohisum(acc[i][1]));
            float2 oB = make_float2(lohisum(acc[i][2]), lohisum(acc[i][3]));
            ((float2*)g_h0)[(size_t)gr * 32 + tx]      = oA;
            ((float2*)g_h0)[(size_t)gr * 32 + 16 + tx] = oB;
        }
    }
}

// ---------------- K3: per-node gather-aggregate, MLP=4 (R13 version) --------
__global__ void __launch_bounds__(256) k_agg() {
    int gw = (blockIdx.x * blockDim.x + threadIdx.x) >> 5;
    if (gw >= NN) return;
    int lane = threadIdx.x & 31;
    int n = gw;
    float dn = g_dinv[n];
    float2 acc = ((const float2*)g_h0)[(size_t)n * 32 + lane];
    float n2 = dn * dn;
    acc.x *= n2;
    acc.y *= n2;

    int o0 = g_off[n];
    int deg = g_deg[n];
    for (int base = 0; base < deg; base += 32) {
        int s = n;
        float wgt = 0.f;
        if (base + lane < deg) {
            s = g_srcs[o0 + base + lane];
            wgt = __ldg(&g_dinv[s]) * dn;
        }
        int cnt = min(32, deg - base);
        for (int j = 0; j < cnt; j += 4) {
            int   s0 = __shfl_sync(0xffffffffu, s, j);
            int   s1 = __shfl_sync(0xffffffffu, s, j + 1);
            int   s2 = __shfl_sync(0xffffffffu, s, j + 2);
            int   s3 = __shfl_sync(0xffffffffu, s, j + 3);
            float n0 = __shfl_sync(0xffffffffu, wgt, j);
            float n1 = __shfl_sync(0xffffffffu, wgt, j + 1);
            float n2_ = __shfl_sync(0xffffffffu, wgt, j + 2);
            float n3 = __shfl_sync(0xffffffffu, wgt, j + 3);
            float2 v0 = ((const float2*)g_h0)[(size_t)s0 * 32 + lane];
            float2 v1 = ((const float2*)g_h0)[(size_t)s1 * 32 + lane];
            float2 v2 = ((const float2*)g_h0)[(size_t)s2 * 32 + lane];
            float2 v3 = ((const float2*)g_h0)[(size_t)s3 * 32 + lane];
            acc.x += v0.x * n0; acc.y += v0.y * n0;
            acc.x += v1.x * n1; acc.y += v1.y * n1;
            acc.x += v2.x * n2_; acc.y += v2.y * n2_;
            acc.x += v3.x * n3; acc.y += v3.y * n3;
        }
    }
    ((float2*)g_agg)[(size_t)n * 32 + lane] = acc;
}

// ---------------- K4: bias+ReLU+LN + tensor GEMM2 (R13 version) -------------
__global__ void __launch_bounds__(256) k_epi(
        const float* __restrict__ bconv, const float* __restrict__ gamma,
        const float* __restrict__ beta, const float* __restrict__ W1,
        const float* __restrict__ b1, float* __restrict__ out) {
    __shared__ __align__(16) float vs[64 * 64];
    __shared__ __align__(16) uint2 W1fh[8 * 8 * 32];
    __shared__ __align__(16) uint2 W1fl[8 * 8 * 32];

    int t = threadIdx.x, lane = t & 31, w = t >> 5;
    int node0 = blockIdx.x * 64;

    if (node0 + 64 > NN) {
        for (int i = t; i < 64 * 64; i += 256) vs[i] = 0.f;
        __syncthreads();
    }

    float2 bc = __ldg((const float2*)bconv + lane);
    float2 gg = __ldg((const float2*)gamma + lane);
    float2 bb = __ldg((const float2*)beta + lane);

#pragma unroll
    for (int s = 0; s < 8; s++) {
        int row = 8 * w + s;
        int node = node0 + row;
        if (node < NN) {
            float2 a = ((const float2*)g_agg)[(size_t)node * 32 + lane];
            a.x = fmaxf(a.x + bc.x, 0.f);
            a.y = fmaxf(a.y + bc.y, 0.f);
            float sm = a.x + a.y, sq = a.x * a.x + a.y * a.y;
#pragma unroll
            for (int o = 16; o; o >>= 1) {
                sm += __shfl_xor_sync(0xffffffffu, sm, o);
                sq += __shfl_xor_sync(0xffffffffu, sq, o);
            }
            float mu = sm * (1.f / 64.f);
            float r = rsqrtf(sq * (1.f / 64.f) - mu * mu + 1e-5f);
            float2 v = make_float2((a.x - mu) * r * gg.x + bb.x,
                                   (a.y - mu) * r * gg.y + bb.y);
            int sw = (2 * lane) ^ (4 * (row & 7));
            *(float2*)&vs[row * 64 + sw] = v;
        }
    }

    int g  = lane >> 2;
    int tg = lane & 3;
    int h  = w >> 2;
    int Gr = 16 * (w & 3);

#pragma unroll
    for (int pass = 0; pass < 2; pass++) {
        int pb = pass * 64;
        __syncthreads();
        for (int i = t; i < 2048; i += 256) {
            int ks  = i >> 8;
            int nbG = (i >> 5) & 7;
            int ln  = i & 31;
            int k1  = ks * 8 + (ln & 3);
            int c   = pb + nbG * 8 + (ln >> 2);
            float bx = __ldg(&W1[k1 * 128 + c]);
            float by = __ldg(&W1[(k1 + 4) * 128 + c]);
            uint32_t hx, lx, hy, ly;
            tfsplit(bx, hx, lx);
            tfsplit(by, hy, ly);
            W1fh[i] = make_uint2(hx, hy);
            W1fl[i] = make_uint2(lx, ly);
        }
        __syncthreads();

        float acc[4][4];
#pragma unroll
        for (int nb = 0; nb < 4; nb++)
#pragma unroll
            for (int i = 0; i < 4; i++) acc[nb][i] = 0.f;

#pragma unroll
        for (int ks = 0; ks < 8; ks++) {
            int kc0 = (ks * 8 + tg)     ^ (4 * g);
            int kc1 = (ks * 8 + tg + 4) ^ (4 * g);
            float af0 = vs[(Gr + g) * 64 + kc0];
            float af1 = vs[(Gr + g + 8) * 64 + kc0];
            float af2 = vs[(Gr + g) * 64 + kc1];
            float af3 = vs[(Gr + g + 8) * 64 + kc1];
            uint32_t ah0, al0, ah1, al1, ah2, al2, ah3, al3;
            tfsplit(af0, ah0, al0);
            tfsplit(af1, ah1, al1);
            tfsplit(af2, ah2, al2);
            tfsplit(af3, ah3, al3);
#pragma unroll
            for (int nb = 0; nb < 4; nb++) {
                int fi = (ks * 8 + 4 * h + nb) * 32 + lane;
                uint2 bh = W1fh[fi];
                uint2 bl = W1fl[fi];
                mma_tf32(acc[nb], ah0, ah1, ah2, ah3, bh.x, bh.y);
                mma_tf32(acc[nb], ah0, ah1, ah2, ah3, bl.x, bl.y);
                mma_tf32(acc[nb], al0, al1, al2, al3, bh.x, bh.y);
            }
        }

#pragma unroll
        for (int nb = 0; nb < 4; nb++) {
            int col = pb + (4 * h + nb) * 8 + 2 * tg;
            float bx = __ldg(&b1[col]);
            float by = __ldg(&b1[col + 1]);
            int nA = node0 + Gr + g;
            int nB = nA + 8;
            if (nA < NN) {
                float2 o = make_float2(fmaxf(acc[nb][0] + bx, 0.f),
                                       fmaxf(acc[nb][1] + by, 0.f));
                *(float2*)&out[(size_t)nA * 128 + col] = o;
            }
            if (nB < NN) {
                float2 o = make_float2(fmaxf(acc[nb][2] + bx, 0.f),
                                       fmaxf(acc[nb][3] + by, 0.f));
                *(float2*)&out[(size_t)nB * 128 + col] = o;
            }
        }
    }
}

// ---------------- launch ----------------
extern "C" void kernel_launch(void* const* d_in, const int* in_sizes, int n_in,
                              void* d_out, int out_size) {
    const float* x      = (const float*)d_in[0];
    const int*   ei     = (const int*)d_in[1];     // int32
    const float* W_conv = (const float*)d_in[2];
    const float* b_conv = (const float*)d_in[3];
    const float* gamma  = (const float*)d_in[4];
    const float* beta   = (const float*)d_in[5];
    const float* W1     = (const float*)d_in[6];
    const float* b1     = (const float*)d_in[7];
    float* out = (float*)d_out;

    void* degp = nullptr;
    cudaGetSymbolAddress(&degp, g_deg);
    cudaMemsetAsync(degp, 0, NN * sizeof(int));

    long long n_h = (long long)NN * H2;
    long long rem = (long long)out_size - n_h;
    int mode = (rem >= (long long)4 * NE) ? 2 : (rem >= (long long)2 * NE) ? 1 : 0;

    k_deg_tail<<<((2 * NE / 4) + 255) / 256, 256>>>(ei, out + n_h, mode);
    k_scan<<<NSCB, 256>>>();
    k_bucket<<<(NE / 4 + 255) / 256, 256>>>(ei);
    k_gemm1<<<(NN + 63) / 64, 256>>>(x, W_conv);
    k_agg<<<(NN * 32 + 255) / 256, 256>>>();
    k_epi<<<(NN + 63) / 64, 256>>>(b_conv, gamma, beta, W1, b1, out);
}

// round 16
// speedup vs baseline: 1.1356x; 1.0519x over previous
#include <cuda_runtime.h>
#include <cstdint>

#define NN   100000
#define NE   1600000
#define HID  64
#define H2   128
#define NSCB 98                       // ceil(NN/1024) scan blocks

typedef unsigned long long ull;

// ---------------- device scratch ----------------
__device__ __align__(16) float g_h0[(size_t)NN * HID];     // x @ W_conv
__device__ __align__(16) float g_agg[(size_t)NN * HID];    // aggregated
__device__ float g_dinv[NN];
__device__ int   g_deg[NN];
__device__ int   g_off[NN];
__device__ int   g_cursor[NN];
__device__ int   g_base;
__device__ int   g_srcs[NE];

// ---------------- tf32 mma helpers ----------------
__device__ __forceinline__ uint32_t f2tf(float x) {
    uint32_t r;
    asm("cvt.rna.tf32.f32 %0, %1;" : "=r"(r) : "f"(x));
    return r;
}
__device__ __forceinline__ void tfsplit(float x, uint32_t& hi, uint32_t& lo) {
    hi = f2tf(x);
    lo = f2tf(x - __uint_as_float(hi));
}
__device__ __forceinline__ void mma_tf32(float* c, uint32_t a0, uint32_t a1,
                                         uint32_t a2, uint32_t a3,
                                         uint32_t b0, uint32_t b1) {
    asm("mma.sync.aligned.m16n8k8.row.col.f32.tf32.tf32.f32 "
        "{%0,%1,%2,%3}, {%4,%5,%6,%7}, {%8,%9}, {%0,%1,%2,%3};"
        : "+f"(c[0]), "+f"(c[1]), "+f"(c[2]), "+f"(c[3])
        : "r"(a0), "r"(a1), "r"(a2), "r"(a3), "r"(b0), "r"(b1));
}

// ---------------- K1: degree + edge_index tail ----------------
__global__ void k_deg_tail(const int* __restrict__ ei, float* __restrict__ tail,
                           int mode) {
    int i4 = blockIdx.x * blockDim.x + threadIdx.x;
    if (i4 == 0) g_base = 0;                           // reset for this launch
    if (i4 >= (2 * NE) / 4) return;
    int4 v = ((const int4*)ei)[i4];
    int base = i4 * 4;
    if (base >= NE) {
        atomicAdd(&g_deg[v.x], 1);
        atomicAdd(&g_deg[v.y], 1);
        atomicAdd(&g_deg[v.z], 1);
        atomicAdd(&g_deg[v.w], 1);
    }
    if (mode == 1) {
        float4 f = make_float4((float)v.x, (float)v.y, (float)v.z, (float)v.w);
        ((float4*)tail)[i4] = f;
    } else if (mode == 2) {
        longlong2 a = make_longlong2((long long)v.x, (long long)v.y);
        longlong2 b = make_longlong2((long long)v.z, (long long)v.w);
        ((longlong2*)tail)[i4 * 2]     = a;
        ((longlong2*)tail)[i4 * 2 + 1] = b;
    }
}

// ---------------- single-kernel scan (also computes dinv) -------------------
__global__ void k_scan() {
    __shared__ int ts[256];
    __shared__ int sbase;
    int b = blockIdx.x, t = threadIdx.x;
    int base = b * 1024 + t * 4;
    int v0 = (base + 0 < NN) ? g_deg[base + 0] : 0;
    int v1 = (base + 1 < NN) ? g_deg[base + 1] : 0;
    int v2 = (base + 2 < NN) ? g_deg[base + 2] : 0;
    int v3 = (base + 3 < NN) ? g_deg[base + 3] : 0;
    int s0 = v0, s1 = s0 + v1, s2 = s1 + v2, s3 = s2 + v3;
    ts[t] = s3;
    __syncthreads();
    for (int o = 1; o < 256; o <<= 1) {
        int x = 0;
        if (t >= o) x = ts[t - o];
        __syncthreads();
        if (t >= o) ts[t] += x;
        __syncthreads();
    }
    if (t == 0) sbase = atomicAdd(&g_base, ts[255]);
    __syncthreads();
    int excl = sbase + ((t > 0) ? ts[t - 1] : 0);
    if (base + 0 < NN) { g_off[base + 0] = excl;      g_cursor[base + 0] = excl;
                         g_dinv[base + 0] = rsqrtf((float)v0 + 1.0f); }
    if (base + 1 < NN) { g_off[base + 1] = excl + s0; g_cursor[base + 1] = excl + s0;
                         g_dinv[base + 1] = rsqrtf((float)v1 + 1.0f); }
    if (base + 2 < NN) { g_off[base + 2] = excl + s1; g_cursor[base + 2] = excl + s1;
                         g_dinv[base + 2] = rsqrtf((float)v2 + 1.0f); }
    if (base + 3 < NN) { g_off[base + 3] = excl + s2; g_cursor[base + 3] = excl + s2;
                         g_dinv[base + 3] = rsqrtf((float)v3 + 1.0f); }
}

// ---------------- K: bucket edges by dst (4 edges/thread) -------------------
__global__ void k_bucket(const int* __restrict__ ei) {
    int i4 = blockIdx.x * blockDim.x + threadIdx.x;
    if (i4 >= NE / 4) return;
    int4 s = ((const int4*)ei)[i4];
    int4 d = ((const int4*)(ei + NE))[i4];
    int p0 = atomicAdd(&g_cursor[d.x], 1);
    int p1 = atomicAdd(&g_cursor[d.y], 1);
    int p2 = atomicAdd(&g_cursor[d.z], 1);
    int p3 = atomicAdd(&g_cursor[d.w], 1);
    g_srcs[p0] = s.x;
    g_srcs[p1] = s.y;
    g_srcs[p2] = s.z;
    g_srcs[p3] = s.w;
}

// ---------------- K2: gemm1 via tensor cores (3xTF32) -----------------------
// h0[64 rows x 64 cols per block] = x @ W_conv. Same mma structure as k_epi's
// GEMM phase (single 64-col pass). A = x tile in swizzled vs; B = W_conv
// fragments pre-split at staging.
__global__ void __launch_bounds__(256) k_gemm1t(
        const float* __restrict__ x, const float* __restrict__ W) {
    __shared__ __align__(16) float vs[64 * 64];      // 16KB
    __shared__ __align__(16) uint2 Wfh[8 * 8 * 32];  // 16KB
    __shared__ __align__(16) uint2 Wfl[8 * 8 * 32];  // 16KB  -> 48KB total

    int t = threadIdx.x, lane = t & 31, w = t >> 5;
    int node0 = blockIdx.x * 64;

    if (node0 + 64 > NN) {
        for (int i = t; i < 64 * 64; i += 256) vs[i] = 0.f;
        __syncthreads();
    }

    // stage + split W fragments: (ks,nbG,ln) -> {W[k1][c], W[k1+4][c]}
    for (int i = t; i < 2048; i += 256) {
        int ks  = i >> 8;
        int nbG = (i >> 5) & 7;
        int ln  = i & 31;
        int k1  = ks * 8 + (ln & 3);
        int c   = nbG * 8 + (ln >> 2);
        float bx = __ldg(&W[k1 * 64 + c]);
        float by = __ldg(&W[(k1 + 4) * 64 + c]);
        uint32_t hx, lx, hy, ly;
        tfsplit(bx, hx, lx);
        tfsplit(by, hy, ly);
        Wfh[i] = make_uint2(hx, hy);
        Wfl[i] = make_uint2(lx, ly);
    }

    // load x tile into swizzled vs: warp w -> rows 8w..8w+7, lane -> 2 cols
#pragma unroll
    for (int s = 0; s < 8; s++) {
        int row = 8 * w + s;
        int node = node0 + row;
        if (node < NN) {
            float2 v = ((const float2*)x)[(size_t)node * 32 + lane];
            int sw = (2 * lane) ^ (4 * (row & 7));
            *(float2*)&vs[row * 64 + sw] = v;
        }
    }
    __syncthreads();

    int g  = lane >> 2;
    int tg = lane & 3;
    int h  = w >> 2;                // 32-col half
    int Gr = 16 * (w & 3);          // warp row base

    float acc[4][4];
#pragma unroll
    for (int nb = 0; nb < 4; nb++)
#pragma unroll
        for (int i = 0; i < 4; i++) acc[nb][i] = 0.f;

#pragma unroll
    for (int ks = 0; ks < 8; ks++) {
        int kc0 = (ks * 8 + tg)     ^ (4 * g);
        int kc1 = (ks * 8 + tg + 4) ^ (4 * g);
        float af0 = vs[(Gr + g) * 64 + kc0];
        float af1 = vs[(Gr + g + 8) * 64 + kc0];
        float af2 = vs[(Gr + g) * 64 + kc1];
        float af3 = vs[(Gr + g + 8) * 64 + kc1];
        uint32_t ah0, al0, ah1, al1, ah2, al2, ah3, al3;
        tfsplit(af0, ah0, al0);
        tfsplit(af1, ah1, al1);
        tfsplit(af2, ah2, al2);
        tfsplit(af3, ah3, al3);
#pragma unroll
        for (int nb = 0; nb < 4; nb++) {
            int fi = (ks * 8 + 4 * h + nb) * 32 + lane;
            uint2 bh = Wfh[fi];
            uint2 bl = Wfl[fi];
            mma_tf32(acc[nb], ah0, ah1, ah2, ah3, bh.x, bh.y);
            mma_tf32(acc[nb], ah0, ah1, ah2, ah3, bl.x, bl.y);
            mma_tf32(acc[nb], al0, al1, al2, al3, bh.x, bh.y);
        }
    }

#pragma unroll
    for (int nb = 0; nb < 4; nb++) {
        int col = (4 * h + nb) * 8 + 2 * tg;
        int nA = node0 + Gr + g;
        int nB = nA + 8;
        if (nA < NN) {
            float2 o = make_float2(acc[nb][0], acc[nb][1]);
            *(float2*)&g_h0[(size_t)nA * 64 + col] = o;
        }
        if (nB < NN) {
            float2 o = make_float2(acc[nb][2], acc[nb][3]);
            *(float2*)&g_h0[(size_t)nB * 64 + col] = o;
        }
    }
}

// ---------------- K3: per-node gather-aggregate, MLP=4 ----------------------
__global__ void __launch_bounds__(256) k_agg() {
    int gw = (blockIdx.x * blockDim.x + threadIdx.x) >> 5;
    if (gw >= NN) return;
    int lane = threadIdx.x & 31;
    int n = gw;
    float dn = g_dinv[n];
    float2 acc = ((const float2*)g_h0)[(size_t)n * 32 + lane];
    float n2 = dn * dn;
    acc.x *= n2;
    acc.y *= n2;

    int o0 = g_off[n];
    int deg = g_deg[n];
    for (int base = 0; base < deg; base += 32) {
        int s = n;
        float wgt = 0.f;
        if (base + lane < deg) {
            s = g_srcs[o0 + base + lane];
            wgt = __ldg(&g_dinv[s]) * dn;
        }
        int cnt = min(32, deg - base);
        for (int j = 0; j < cnt; j += 4) {
            int   s0 = __shfl_sync(0xffffffffu, s, j);
            int   s1 = __shfl_sync(0xffffffffu, s, j + 1);
            int   s2 = __shfl_sync(0xffffffffu, s, j + 2);
            int   s3 = __shfl_sync(0xffffffffu, s, j + 3);
            float n0 = __shfl_sync(0xffffffffu, wgt, j);
            float n1 = __shfl_sync(0xffffffffu, wgt, j + 1);
            float n2_ = __shfl_sync(0xffffffffu, wgt, j + 2);
            float n3 = __shfl_sync(0xffffffffu, wgt, j + 3);
            float2 v0 = ((const float2*)g_h0)[(size_t)s0 * 32 + lane];
            float2 v1 = ((const float2*)g_h0)[(size_t)s1 * 32 + lane];
            float2 v2 = ((const float2*)g_h0)[(size_t)s2 * 32 + lane];
            float2 v3 = ((const float2*)g_h0)[(size_t)s3 * 32 + lane];
            acc.x += v0.x * n0; acc.y += v0.y * n0;
            acc.x += v1.x * n1; acc.y += v1.y * n1;
            acc.x += v2.x * n2_; acc.y += v2.y * n2_;
            acc.x += v3.x * n3; acc.y += v3.y * n3;
        }
    }
    ((float2*)g_agg)[(size_t)n * 32 + lane] = acc;
}

// ---------------- K4: bias+ReLU+LN + tensor GEMM2 (R13 version) -------------
__global__ void __launch_bounds__(256) k_epi(
        const float* __restrict__ bconv, const float* __restrict__ gamma,
        const float* __restrict__ beta, const float* __restrict__ W1,
        const float* __restrict__ b1, float* __restrict__ out) {
    __shared__ __align__(16) float vs[64 * 64];
    __shared__ __align__(16) uint2 W1fh[8 * 8 * 32];
    __shared__ __align__(16) uint2 W1fl[8 * 8 * 32];

    int t = threadIdx.x, lane = t & 31, w = t >> 5;
    int node0 = blockIdx.x * 64;

    if (node0 + 64 > NN) {
        for (int i = t; i < 64 * 64; i += 256) vs[i] = 0.f;
        __syncthreads();
    }

    float2 bc = __ldg((const float2*)bconv + lane);
    float2 gg = __ldg((const float2*)gamma + lane);
    float2 bb = __ldg((const float2*)beta + lane);

#pragma unroll
    for (int s = 0; s < 8; s++) {
        int row = 8 * w + s;
        int node = node0 + row;
        if (node < NN) {
            float2 a = ((const float2*)g_agg)[(size_t)node * 32 + lane];
            a.x = fmaxf(a.x + bc.x, 0.f);
            a.y = fmaxf(a.y + bc.y, 0.f);
            float sm = a.x + a.y, sq = a.x * a.x + a.y * a.y;
#pragma unroll
            for (int o = 16; o; o >>= 1) {
                sm += __shfl_xor_sync(0xffffffffu, sm, o);
                sq += __shfl_xor_sync(0xffffffffu, sq, o);
            }
            float mu = sm * (1.f / 64.f);
            float r = rsqrtf(sq * (1.f / 64.f) - mu * mu + 1e-5f);
            float2 v = make_float2((a.x - mu) * r * gg.x + bb.x,
                                   (a.y - mu) * r * gg.y + bb.y);
            int sw = (2 * lane) ^ (4 * (row & 7));
            *(float2*)&vs[row * 64 + sw] = v;
        }
    }

    int g  = lane >> 2;
    int tg = lane & 3;
    int h  = w >> 2;
    int Gr = 16 * (w & 3);

#pragma unroll
    for (int pass = 0; pass < 2; pass++) {
        int pb = pass * 64;
        __syncthreads();
        for (int i = t; i < 2048; i += 256) {
            int ks  = i >> 8;
            int nbG = (i >> 5) & 7;
            int ln  = i & 31;
            int k1  = ks * 8 + (ln & 3);
            int c   = pb + nbG * 8 + (ln >> 2);
            float bx = __ldg(&W1[k1 * 128 + c]);
            float by = __ldg(&W1[(k1 + 4) * 128 + c]);
            uint32_t hx, lx, hy, ly;
            tfsplit(bx, hx, lx);
            tfsplit(by, hy, ly);
            W1fh[i] = make_uint2(hx, hy);
            W1fl[i] = make_uint2(lx, ly);
        }
        __syncthreads();

        float acc[4][4];
#pragma unroll
        for (int nb = 0; nb < 4; nb++)
#pragma unroll
            for (int i = 0; i < 4; i++) acc[nb][i] = 0.f;

#pragma unroll
        for (int ks = 0; ks < 8; ks++) {
            int kc0 = (ks * 8 + tg)     ^ (4 * g);
            int kc1 = (ks * 8 + tg + 4) ^ (4 * g);
            float af0 = vs[(Gr + g) * 64 + kc0];
            float af1 = vs[(Gr + g + 8) * 64 + kc0];
            float af2 = vs[(Gr + g) * 64 + kc1];
            float af3 = vs[(Gr + g + 8) * 64 + kc1];
            uint32_t ah0, al0, ah1, al1, ah2, al2, ah3, al3;
            tfsplit(af0, ah0, al0);
            tfsplit(af1, ah1, al1);
            tfsplit(af2, ah2, al2);
            tfsplit(af3, ah3, al3);
#pragma unroll
            for (int nb = 0; nb < 4; nb++) {
                int fi = (ks * 8 + 4 * h + nb) * 32 + lane;
                uint2 bh = W1fh[fi];
                uint2 bl = W1fl[fi];
                mma_tf32(acc[nb], ah0, ah1, ah2, ah3, bh.x, bh.y);
                mma_tf32(acc[nb], ah0, ah1, ah2, ah3, bl.x, bl.y);
                mma_tf32(acc[nb], al0, al1, al2, al3, bh.x, bh.y);
            }
        }

#pragma unroll
        for (int nb = 0; nb < 4; nb++) {
            int col = pb + (4 * h + nb) * 8 + 2 * tg;
            float bx = __ldg(&b1[col]);
            float by = __ldg(&b1[col + 1]);
            int nA = node0 + Gr + g;
            int nB = nA + 8;
            if (nA < NN) {
                float2 o = make_float2(fmaxf(acc[nb][0] + bx, 0.f),
                                       fmaxf(acc[nb][1] + by, 0.f));
                *(float2*)&out[(size_t)nA * 128 + col] = o;
            }
            if (nB < NN) {
                float2 o = make_float2(fmaxf(acc[nb][2] + bx, 0.f),
                                       fmaxf(acc[nb][3] + by, 0.f));
                *(float2*)&out[(size_t)nB * 128 + col] = o;
            }
        }
    }
}

// ---------------- launch ----------------
extern "C" void kernel_launch(void* const* d_in, const int* in_sizes, int n_in,
                              void* d_out, int out_size) {
    const float* x      = (const float*)d_in[0];
    const int*   ei     = (const int*)d_in[1];     // int32
    const float* W_conv = (const float*)d_in[2];
    const float* b_conv = (const float*)d_in[3];
    const float* gamma  = (const float*)d_in[4];
    const float* beta   = (const float*)d_in[5];
    const float* W1     = (const float*)d_in[6];
    const float* b1     = (const float*)d_in[7];
    float* out = (float*)d_out;

    void* degp = nullptr;
    cudaGetSymbolAddress(&degp, g_deg);
    cudaMemsetAsync(degp, 0, NN * sizeof(int));

    long long n_h = (long long)NN * H2;
    long long rem = (long long)out_size - n_h;
    int mode = (rem >= (long long)4 * NE) ? 2 : (rem >= (long long)2 * NE) ? 1 : 0;

    k_deg_tail<<<((2 * NE / 4) + 255) / 256, 256>>>(ei, out + n_h, mode);
    k_scan<<<NSCB, 256>>>();
    k_bucket<<<(NE / 4 + 255) / 256, 256>>>(ei);
    k_gemm1t<<<(NN + 63) / 64, 256>>>(x, W_conv);
    k_agg<<<(NN * 32 + 255) / 256, 256>>>();
    k_epi<<<(NN + 63) / 64, 256>>>(b_conv, gamma, beta, W1, b1, out);
}